// round 12
// baseline (speedup 1.0000x reference)
#include <cuda_runtime.h>
#include <cstdint>

#define GN    8192
#define ROWS  2
#define LMBD  0.1f
#define QCAP  64
#define QEFF  (QCAP - 4)
#define FULLM 0xffffffffu

__device__ float    g_sum;     // zero-init; reset by last block each launch
__device__ unsigned g_count;

__device__ __forceinline__ void cpa16(uint32_t dst_smem, const void* src) {
    asm volatile("cp.async.cg.shared.global [%0], [%1], 16;"
                 :: "r"(dst_smem), "l"(src));
}

// R11 (67.6us) + 2-row software pipeline: while row r drains, row r+1's
// cp.async transfer is in flight -> DRAM stays busy through the drain phase.
// Block handles 2 consecutive rows; warp w owns cols [w*1024,(w+1)*1024).
// Per row: W/b L2 loads + yi/ci/rn setup overlap the in-flight cp.async;
// wait; compact from smem (1 ballot/float4, first nz queued as scalar (a,j),
// extras/overflow inline); issue next row's cp.async; drain (16-lane dot
// groups, 4 entries/iter, 8 W-loads batched). b folded: pred = W[j].Y[i]+ci.
__global__ void __launch_bounds__(256, 6)
main_kernel(const float* __restrict__ A, const float* __restrict__ W,
            const float* __restrict__ b, float* __restrict__ out) {
    __shared__ float4 stage[8][256];   // 8 warps x 4KB (single buffer, reused)
    __shared__ float qa[8][QCAP];
    __shared__ int   qj[8][QCAP];
    __shared__ float sp[8];

    const int w    = threadIdx.x >> 5;
    const int lane = threadIdx.x & 31;
    const int hl   = lane & 15;    // lane within 16-lane group
    const int grp  = lane >> 4;    // group 0..1
    const unsigned ltm = (1u << lane) - 1u;

    const float4* __restrict__ A4 = reinterpret_cast<const float4*>(A);
    const float4* __restrict__ W4 = reinterpret_cast<const float4*>(W);
    const float4* __restrict__ B4 = reinterpret_cast<const float4*>(b);

    const int row0  = blockIdx.x * ROWS;
    const int base4 = w * 256;

    const uint32_t sdst =
        (uint32_t)__cvta_generic_to_shared(&stage[w][lane]);

    auto issueA = [&](int row) {
        const float4* gsrc = A4 + (size_t)row * (GN / 4) + base4 + lane;
        #pragma unroll
        for (int k = 0; k < 8; k++)
            cpa16(sdst + k * 512, gsrc + k * 32);
        asm volatile("cp.async.commit_group;");
    };

    // get row0's 4KB segment moving immediately
    issueA(row0);

    float acc = 0.f;
    float4 yi0, yi1;
    float  ci;

    // reduce 8 per-lane products over the 16-lane group (valid on all lanes)
    auto dot8 = [&](float4 z0, float4 z1) -> float {
        float p = z0.x*yi0.x + z0.y*yi0.y + z0.z*yi0.z + z0.w*yi0.w
                + z1.x*yi1.x + z1.y*yi1.y + z1.z*yi1.z + z1.w*yi1.w;
        p += __shfl_xor_sync(FULLM, p, 1);
        p += __shfl_xor_sync(FULLM, p, 2);
        p += __shfl_xor_sync(FULLM, p, 4);
        p += __shfl_xor_sync(FULLM, p, 8);
        return p;
    };

    int cnt = 0;   // warp-uniform

    // compact one float4: queue first nz as scalar; extras/overflow inline
    auto compact = [&](float4 a4, int g4) {
        unsigned nzm = (a4.x > 0.f ? 1u : 0u) | (a4.y > 0.f ? 2u : 0u)
                     | (a4.z > 0.f ? 4u : 0u) | (a4.w > 0.f ? 8u : 0u);
        bool nz = nzm != 0u;
        unsigned m = __ballot_sync(FULLM, nz);
        if (m == 0) return;

        int e0 = __ffs(nzm) - 1;
        float a0 = (e0 <= 0) ? a4.x : (e0 == 1) ? a4.y
                 : (e0 == 2) ? a4.z : a4.w;
        int pos = cnt + __popc(m & ltm);
        bool ovf = nz && pos >= QEFF;
        if (nz && !ovf) { qa[w][pos] = a0; qj[w][pos] = g4 * 4 + e0; }

        unsigned extra = nz ? (nzm & (nzm - 1u)) : 0u;
        unsigned mo = __ballot_sync(FULLM, (extra != 0u) | ovf);
        cnt = min(cnt + __popc(m), QEFF);
        while (mo) {   // rare
            int src = __ffs(mo) - 1; mo &= mo - 1;
            float bx = __shfl_sync(FULLM, a4.x, src);
            float by = __shfl_sync(FULLM, a4.y, src);
            float bz = __shfl_sync(FULLM, a4.z, src);
            float bw = __shfl_sync(FULLM, a4.w, src);
            unsigned em = __shfl_sync(FULLM, extra, src);
            unsigned nm = __shfl_sync(FULLM, nzm, src);
            int  ov = __shfl_sync(FULLM, (int)ovf, src);
            int  jb = __shfl_sync(FULLM, g4, src) * 4;
            unsigned todo = ov ? nm : em;
            while (todo) {
                int e = __ffs(todo) - 1; todo &= todo - 1;
                float a = (e == 0) ? bx : (e == 1) ? by : (e == 2) ? bz : bw;
                const float4* yr = W4 + (jb + e) * 32 + hl;
                float p = dot8(yr[0], yr[16]);   // same j both groups -> full dot
                if (lane == 0) {
                    float rr = a - (p + ci);
                    acc = fmaf(0.5f * rr, rr, acc);
                }
            }
        }
    };

    // drain queue: 4 entries per iteration, all 8 W-loads before any reduce
    auto drain = [&]() {
        int cntp = (cnt + 3) & ~3;
        if (lane < cntp - cnt) { qa[w][cnt + lane] = 0.f; qj[w][cnt + lane] = 0; }
        __syncwarp();
        for (int base = 0; base < cntp; base += 4) {
            float aA = qa[w][base + grp];       int jA = qj[w][base + grp];
            float aB = qa[w][base + 2 + grp];   int jB = qj[w][base + 2 + grp];
            const float4* ya = W4 + jA * 32 + hl;
            const float4* yb = W4 + jB * 32 + hl;
            float4 za0 = ya[0],  za1 = ya[16];
            float4 zb0 = yb[0],  zb1 = yb[16];
            float pA = dot8(za0, za1);
            if (aA > 0.f && hl == 0) {
                float rr = aA - (pA + ci);
                acc = fmaf(0.5f * rr, rr, acc);
            }
            float pB = dot8(zb0, zb1);
            if (aB > 0.f && hl == 0) {
                float rr = aB - (pB + ci);
                acc = fmaf(0.5f * rr, rr, acc);
            }
        }
        __syncwarp();
        cnt = 0;
    };

    #pragma unroll
    for (int r = 0; r < ROWS; r++) {
        const int row = row0 + r;

        // yi = W[row]+b setup (L2 loads + shuffle chain) overlaps the
        // in-flight cp.async of this row's A segment.
        float rn;
        {
            float4 wv0 = W4[row * 32 + hl],      bv0 = B4[hl];
            float4 wv1 = W4[row * 32 + 16 + hl], bv1 = B4[16 + hl];
            yi0.x = wv0.x + bv0.x; yi0.y = wv0.y + bv0.y;
            yi0.z = wv0.z + bv0.z; yi0.w = wv0.w + bv0.w;
            yi1.x = wv1.x + bv1.x; yi1.y = wv1.y + bv1.y;
            yi1.z = wv1.z + bv1.z; yi1.w = wv1.w + bv1.w;
            ci = bv0.x*yi0.x + bv0.y*yi0.y + bv0.z*yi0.z + bv0.w*yi0.w
               + bv1.x*yi1.x + bv1.y*yi1.y + bv1.z*yi1.z + bv1.w*yi1.w;
            rn = yi0.x*yi0.x + yi0.y*yi0.y + yi0.z*yi0.z + yi0.w*yi0.w
               + yi1.x*yi1.x + yi1.y*yi1.y + yi1.z*yi1.z + yi1.w*yi1.w;
            #pragma unroll
            for (int off = 1; off < 16; off <<= 1) {
                ci += __shfl_xor_sync(FULLM, ci, off);
                rn += __shfl_xor_sync(FULLM, rn, off);
            }
        }
        if (w == 0 && lane == 0) acc = fmaf(0.5f * LMBD, rn, acc);

        // wait for this row's A segment, compact it out of the stage
        asm volatile("cp.async.wait_group 0;");
        __syncwarp();
        #pragma unroll
        for (int k = 0; k < 8; k++) {
            float4 a4 = stage[w][k * 32 + lane];
            compact(a4, base4 + k * 32 + lane);
        }

        // stage now fully consumed: get next row's DRAM transfer in flight
        if (r + 1 < ROWS) issueA(row + 1);

        // drain this row's nonzeros while next row's A streams in
        drain();
    }

    // block reduce (acc lives on lanes 0 and 16)
    #pragma unroll
    for (int off = 16; off > 0; off >>= 1)
        acc += __shfl_xor_sync(FULLM, acc, off);
    if (lane == 0) sp[w] = acc;
    __syncthreads();

    if (threadIdx.x == 0) {
        float part = 0.f;
        #pragma unroll
        for (int i = 0; i < 8; i++) part += sp[i];
        atomicAdd(&g_sum, part);
        __threadfence();
        unsigned c = atomicAdd(&g_count, 1u);
        if (c == gridDim.x - 1) {
            float total = atomicExch(&g_sum, 0.f);
            atomicExch(&g_count, 0u);
            out[0] = total;
        }
    }
}

extern "C" void kernel_launch(void* const* d_in, const int* in_sizes, int n_in,
                              void* d_out, int out_size) {
    const float* A = (const float*)d_in[0];
    const float* W = (const float*)d_in[1];
    const float* b = (const float*)d_in[2];
    float* out = (float*)d_out;

    main_kernel<<<GN / ROWS, 256>>>(A, W, b, out);
}

// round 13
// speedup vs baseline: 1.1395x; 1.1395x over previous
#include <cuda_runtime.h>
#include <cstdint>

#define GN    8192
#define LMBD  0.1f
#define QCAP  64
#define QEFF  (QCAP - 4)
#define FULLM 0xffffffffu

__device__ float    g_sum;     // zero-init; reset by last block each launch
__device__ unsigned g_count;

__device__ __forceinline__ void cpa16(uint32_t dst_smem, const void* src) {
    asm volatile("cp.async.cg.shared.global [%0], [%1], 16;"
                 :: "r"(dst_smem), "l"(src));
}
__device__ __forceinline__ uint64_t mul2(uint64_t a, uint64_t b) {
    uint64_t d; asm("mul.rn.f32x2 %0,%1,%2;" : "=l"(d) : "l"(a), "l"(b));
    return d;
}
__device__ __forceinline__ uint64_t fma2(uint64_t a, uint64_t b, uint64_t c) {
    uint64_t d; asm("fma.rn.f32x2 %0,%1,%2,%3;" : "=l"(d) : "l"(a), "l"(b), "l"(c));
    return d;
}
__device__ __forceinline__ uint64_t packf2(float lo, float hi) {
    uint64_t d; asm("mov.b64 %0,{%1,%2};" : "=l"(d) : "f"(lo), "f"(hi));
    return d;
}
__device__ __forceinline__ float unpack_sum(uint64_t v) {
    float lo, hi; asm("mov.b64 {%0,%1},%2;" : "=f"(lo), "=f"(hi) : "l"(v));
    return lo + hi;
}

// R11 structure (best measured: 67.6us), issue-slot optimized:
//  - dot uses packed fma.rn.f32x2 (4 ops instead of 8 FMAs)
//  - rn folded per-lane into acc (no rn shuffle chain)
//  - queue entries fused to one float2 (1x LDS.64), j stored pre-multiplied
// One block per row (8192 x 256). Warp w owns cols [w*1024,(w+1)*1024).
// W/b L2 loads first (L1tex FIFO), then 8x cp.async 16B stage the 4KB A
// segment while the setup chain runs. Compact: 1 ballot/float4, first nz
// queued; extras/overflow inline. Drain: 16-lane dot groups, 4 entries/iter,
// all 8 W-loads batched before reduces. b folded: pred = W[j].Y[i] + ci.
__global__ void __launch_bounds__(256, 6)
main_kernel(const float* __restrict__ A, const float* __restrict__ W,
            const float* __restrict__ b, float* __restrict__ out) {
    __shared__ float4 stage[8][256];   // 8 warps x 4KB
    __shared__ float2 q[8][QCAP];      // (a, bits(j*32))
    __shared__ float  sp[8];

    const int row  = blockIdx.x;
    const int w    = threadIdx.x >> 5;
    const int lane = threadIdx.x & 31;
    const int hl   = lane & 15;    // lane within 16-lane group
    const int grp  = lane >> 4;    // group 0..1
    const unsigned ltm = (1u << lane) - 1u;

    const float4* __restrict__ A4 =
        reinterpret_cast<const float4*>(A) + (size_t)row * (GN / 4);
    const float4* __restrict__ W4 = reinterpret_cast<const float4*>(W);
    const float4* __restrict__ B4 = reinterpret_cast<const float4*>(b);

    const int base4 = w * 256;

    // L2 loads FIRST (drain early from the in-order L1tex queue) ...
    float4 wv0 = W4[row * 32 + hl];
    float4 wv1 = W4[row * 32 + 16 + hl];
    float4 bv0 = B4[hl];
    float4 bv1 = B4[16 + hl];

    // ... then stream the whole 4KB A segment to smem (MLP=8)
    {
        uint32_t sdst = (uint32_t)__cvta_generic_to_shared(&stage[w][lane]);
        const float4* gsrc = A4 + base4 + lane;
        #pragma unroll
        for (int k = 0; k < 8; k++)
            cpa16(sdst + k * 512, gsrc + k * 32);
        asm volatile("cp.async.commit_group;");
    }

    // yi = W[row]+b; ci = b.yi (4-shfl chain); rn folded per-lane (no chain).
    float acc = 0.f;
    uint64_t yp0, yp1, yp2, yp3;
    float ci;
    {
        float4 yi0, yi1;
        yi0.x = wv0.x + bv0.x; yi0.y = wv0.y + bv0.y;
        yi0.z = wv0.z + bv0.z; yi0.w = wv0.w + bv0.w;
        yi1.x = wv1.x + bv1.x; yi1.y = wv1.y + bv1.y;
        yi1.z = wv1.z + bv1.z; yi1.w = wv1.w + bv1.w;
        ci = bv0.x*yi0.x + bv0.y*yi0.y + bv0.z*yi0.z + bv0.w*yi0.w
           + bv1.x*yi1.x + bv1.y*yi1.y + bv1.z*yi1.z + bv1.w*yi1.w;
        #pragma unroll
        for (int off = 1; off < 16; off <<= 1)
            ci += __shfl_xor_sync(FULLM, ci, off);

        // reg loss: per-lane partial, summed by the final block butterfly
        if (w == 0 && lane < 16) {
            float rl = yi0.x*yi0.x + yi0.y*yi0.y + yi0.z*yi0.z + yi0.w*yi0.w
                     + yi1.x*yi1.x + yi1.y*yi1.y + yi1.z*yi1.z + yi1.w*yi1.w;
            acc = 0.5f * LMBD * rl;
        }
        yp0 = packf2(yi0.x, yi0.y); yp1 = packf2(yi0.z, yi0.w);
        yp2 = packf2(yi1.x, yi1.y); yp3 = packf2(yi1.z, yi1.w);
    }

    // 16-lane-group dot via packed f32x2 (valid on all lanes after reduce)
    auto dot8 = [&](ulonglong2 z0, ulonglong2 z1) -> float {
        uint64_t t = mul2(z0.x, yp0);
        t = fma2(z0.y, yp1, t);
        t = fma2(z1.x, yp2, t);
        t = fma2(z1.y, yp3, t);
        float p = unpack_sum(t);
        p += __shfl_xor_sync(FULLM, p, 1);
        p += __shfl_xor_sync(FULLM, p, 2);
        p += __shfl_xor_sync(FULLM, p, 4);
        p += __shfl_xor_sync(FULLM, p, 8);
        return p;
    };
    const ulonglong2* __restrict__ WU =
        reinterpret_cast<const ulonglong2*>(W4);

    int cnt = 0;   // warp-uniform

    // compact one float4: queue first nz as (a, j*32); extras/overflow inline
    auto compact = [&](float4 a4, int g4) {
        unsigned nzm = (a4.x > 0.f ? 1u : 0u) | (a4.y > 0.f ? 2u : 0u)
                     | (a4.z > 0.f ? 4u : 0u) | (a4.w > 0.f ? 8u : 0u);
        bool nz = nzm != 0u;
        unsigned m = __ballot_sync(FULLM, nz);
        if (m == 0) return;

        int e0 = __ffs(nzm) - 1;
        float a0 = (e0 <= 0) ? a4.x : (e0 == 1) ? a4.y
                 : (e0 == 2) ? a4.z : a4.w;
        int pos = cnt + __popc(m & ltm);
        bool ovf = nz && pos >= QEFF;
        if (nz && !ovf)
            q[w][pos] = make_float2(a0, __int_as_float((g4 * 4 + e0) * 32));

        unsigned extra = nz ? (nzm & (nzm - 1u)) : 0u;
        unsigned mo = __ballot_sync(FULLM, (extra != 0u) | ovf);
        cnt = min(cnt + __popc(m), QEFF);
        while (mo) {   // rare
            int src = __ffs(mo) - 1; mo &= mo - 1;
            float bx = __shfl_sync(FULLM, a4.x, src);
            float by = __shfl_sync(FULLM, a4.y, src);
            float bz = __shfl_sync(FULLM, a4.z, src);
            float bw = __shfl_sync(FULLM, a4.w, src);
            unsigned em = __shfl_sync(FULLM, extra, src);
            unsigned nm = __shfl_sync(FULLM, nzm, src);
            int  ov = __shfl_sync(FULLM, (int)ovf, src);
            int  jb = __shfl_sync(FULLM, g4, src) * 4;
            unsigned todo = ov ? nm : em;
            while (todo) {
                int e = __ffs(todo) - 1; todo &= todo - 1;
                float a = (e == 0) ? bx : (e == 1) ? by : (e == 2) ? bz : bw;
                const ulonglong2* yr = WU + (jb + e) * 32 + hl;
                float p = dot8(yr[0], yr[16]);   // same j all lanes -> full dot
                if (lane == 0) {
                    float rr = a - (p + ci);
                    acc = fmaf(0.5f * rr, rr, acc);
                }
            }
        }
    };

    // wait for the A segment, then compact all 8 float4 groups from smem
    asm volatile("cp.async.wait_group 0;");
    __syncwarp();
    #pragma unroll
    for (int k = 0; k < 8; k++) {
        float4 a4 = stage[w][k * 32 + lane];
        compact(a4, base4 + k * 32 + lane);
    }

    // single drain: 4 entries per iteration, all 8 W-loads before any reduce
    {
        int cntp = (cnt + 3) & ~3;
        if (lane < cntp - cnt) q[w][cnt + lane] = make_float2(0.f, 0.f);
        __syncwarp();
        for (int base = 0; base < cntp; base += 4) {
            float2 eA = q[w][base + grp];       // 1x LDS.64 each
            float2 eB = q[w][base + 2 + grp];
            int jA = __float_as_int(eA.y);
            int jB = __float_as_int(eB.y);
            const ulonglong2* ya = WU + jA + hl;
            const ulonglong2* yb = WU + jB + hl;
            ulonglong2 za0 = ya[0], za1 = ya[16];
            ulonglong2 zb0 = yb[0], zb1 = yb[16];
            float pA = dot8(za0, za1);
            if (eA.x > 0.f && hl == 0) {
                float rr = eA.x - (pA + ci);
                acc = fmaf(0.5f * rr, rr, acc);
            }
            float pB = dot8(zb0, zb1);
            if (eB.x > 0.f && hl == 0) {
                float rr = eB.x - (pB + ci);
                acc = fmaf(0.5f * rr, rr, acc);
            }
        }
    }

    // block reduce (sums per-lane rl partials + per-group dot partials)
    #pragma unroll
    for (int off = 16; off > 0; off >>= 1)
        acc += __shfl_xor_sync(FULLM, acc, off);
    if (lane == 0) sp[w] = acc;
    __syncthreads();

    if (threadIdx.x == 0) {
        float part = 0.f;
        #pragma unroll
        for (int i = 0; i < 8; i++) part += sp[i];
        atomicAdd(&g_sum, part);
        __threadfence();
        unsigned c = atomicAdd(&g_count, 1u);
        if (c == gridDim.x - 1) {
            float total = atomicExch(&g_sum, 0.f);
            atomicExch(&g_count, 0u);
            out[0] = total;
        }
    }
}

extern "C" void kernel_launch(void* const* d_in, const int* in_sizes, int n_in,
                              void* d_out, int out_size) {
    const float* A = (const float*)d_in[0];
    const float* W = (const float*)d_in[1];
    const float* b = (const float*)d_in[2];
    float* out = (float*)d_out;

    main_kernel<<<GN, 256>>>(A, W, b, out);
}

// round 14
// speedup vs baseline: 1.1981x; 1.0515x over previous
#include <cuda_runtime.h>
#include <cstdint>

#define GN    8192
#define LMBD  0.1f
#define QCAP  64
#define QEFF  (QCAP - 4)
#define FULLM 0xffffffffu

__device__ float    g_sum;     // zero-init; reset by last block each launch
__device__ unsigned g_count;

__device__ __forceinline__ void cpa16(uint32_t dst_smem, const void* src) {
    asm volatile("cp.async.cg.shared.global [%0], [%1], 16;"
                 :: "r"(dst_smem), "l"(src));
}
__device__ __forceinline__ uint64_t mul2(uint64_t a, uint64_t b) {
    uint64_t d; asm("mul.rn.f32x2 %0,%1,%2;" : "=l"(d) : "l"(a), "l"(b));
    return d;
}
__device__ __forceinline__ uint64_t fma2(uint64_t a, uint64_t b, uint64_t c) {
    uint64_t d; asm("fma.rn.f32x2 %0,%1,%2,%3;" : "=l"(d) : "l"(a), "l"(b), "l"(c));
    return d;
}
__device__ __forceinline__ uint64_t packf2(float lo, float hi) {
    uint64_t d; asm("mov.b64 %0,{%1,%2};" : "=l"(d) : "f"(lo), "f"(hi));
    return d;
}
__device__ __forceinline__ float unpack_sum(uint64_t v) {
    float lo, hi; asm("mov.b64 {%0,%1},%2;" : "=f"(lo), "=f"(hi) : "l"(v));
    return lo + hi;
}

// R13 (best: 65.4us) with two changes:
//  - A stage split into 2 commit groups (2KB each): wait_group(1) starts
//    compact after the first half lands; second half streams during compact.
//  - extras/overflow ballot deferred to once per half (4 float4s); slow path
//    reloads A from the smem stage (no data shuffles).
// One block per row (8192 x 256). Warp w owns cols [w*1024,(w+1)*1024).
// Compact: 1 ballot/float4, first nz queued as (a, j*32) float2. Drain:
// 16-lane dot groups, 4 entries/iter, all 8 W-loads batched, packed f32x2
// dot, 4-shfl reduce. b folded: pred = W[j].Y[i] + ci.
__global__ void __launch_bounds__(256, 6)
main_kernel(const float* __restrict__ A, const float* __restrict__ W,
            const float* __restrict__ b, float* __restrict__ out) {
    __shared__ float4 stage[8][256];   // 8 warps x 4KB
    __shared__ float2 q[8][QCAP];      // (a, bits(j*32))
    __shared__ float  sp[8];

    const int row  = blockIdx.x;
    const int w    = threadIdx.x >> 5;
    const int lane = threadIdx.x & 31;
    const int hl   = lane & 15;    // lane within 16-lane group
    const int grp  = lane >> 4;    // group 0..1
    const unsigned ltm = (1u << lane) - 1u;

    const float4* __restrict__ A4 =
        reinterpret_cast<const float4*>(A) + (size_t)row * (GN / 4);
    const float4* __restrict__ W4 = reinterpret_cast<const float4*>(W);
    const float4* __restrict__ B4 = reinterpret_cast<const float4*>(b);

    const int base4 = w * 256;

    // L2 loads FIRST (drain early from the in-order L1tex queue) ...
    float4 wv0 = W4[row * 32 + hl];
    float4 wv1 = W4[row * 32 + 16 + hl];
    float4 bv0 = B4[hl];
    float4 bv1 = B4[16 + hl];

    // ... then stream the 4KB A segment as TWO 2KB commit groups
    {
        uint32_t sdst = (uint32_t)__cvta_generic_to_shared(&stage[w][lane]);
        const float4* gsrc = A4 + base4 + lane;
        #pragma unroll
        for (int k = 0; k < 4; k++) cpa16(sdst + k * 512, gsrc + k * 32);
        asm volatile("cp.async.commit_group;");
        #pragma unroll
        for (int k = 4; k < 8; k++) cpa16(sdst + k * 512, gsrc + k * 32);
        asm volatile("cp.async.commit_group;");
    }

    // yi = W[row]+b; ci = b.yi (4-shfl chain); rn folded per-lane (no chain).
    float acc = 0.f;
    uint64_t yp0, yp1, yp2, yp3;
    float ci;
    {
        float4 yi0, yi1;
        yi0.x = wv0.x + bv0.x; yi0.y = wv0.y + bv0.y;
        yi0.z = wv0.z + bv0.z; yi0.w = wv0.w + bv0.w;
        yi1.x = wv1.x + bv1.x; yi1.y = wv1.y + bv1.y;
        yi1.z = wv1.z + bv1.z; yi1.w = wv1.w + bv1.w;
        ci = bv0.x*yi0.x + bv0.y*yi0.y + bv0.z*yi0.z + bv0.w*yi0.w
           + bv1.x*yi1.x + bv1.y*yi1.y + bv1.z*yi1.z + bv1.w*yi1.w;
        #pragma unroll
        for (int off = 1; off < 16; off <<= 1)
            ci += __shfl_xor_sync(FULLM, ci, off);

        if (w == 0 && lane < 16) {   // reg loss: per-lane, summed at the end
            float rl = yi0.x*yi0.x + yi0.y*yi0.y + yi0.z*yi0.z + yi0.w*yi0.w
                     + yi1.x*yi1.x + yi1.y*yi1.y + yi1.z*yi1.z + yi1.w*yi1.w;
            acc = 0.5f * LMBD * rl;
        }
        yp0 = packf2(yi0.x, yi0.y); yp1 = packf2(yi0.z, yi0.w);
        yp2 = packf2(yi1.x, yi1.y); yp3 = packf2(yi1.z, yi1.w);
    }

    // 16-lane-group dot via packed f32x2 (valid on all lanes after reduce)
    auto dot8 = [&](ulonglong2 z0, ulonglong2 z1) -> float {
        uint64_t t = mul2(z0.x, yp0);
        t = fma2(z0.y, yp1, t);
        t = fma2(z1.x, yp2, t);
        t = fma2(z1.y, yp3, t);
        float p = unpack_sum(t);
        p += __shfl_xor_sync(FULLM, p, 1);
        p += __shfl_xor_sync(FULLM, p, 2);
        p += __shfl_xor_sync(FULLM, p, 4);
        p += __shfl_xor_sync(FULLM, p, 8);
        return p;
    };
    const ulonglong2* __restrict__ WU =
        reinterpret_cast<const ulonglong2*>(W4);

    int cnt = 0;   // warp-uniform

    // compact 4 float4 groups [kbase, kbase+4); extras/overflow deferred to
    // ONE ballot; slow path reloads A from the smem stage (no data shuffles).
    auto compact_half = [&](int kbase) {
        unsigned exm = 0u;   // 4 bits per k-slot: extra-component masks
        unsigned ovm = 0u;   // 1 bit per k-slot: overflow
        #pragma unroll
        for (int kk = 0; kk < 4; kk++) {
            const int k = kbase + kk;
            float4 a4 = stage[w][k * 32 + lane];
            unsigned nzm = (a4.x > 0.f ? 1u : 0u) | (a4.y > 0.f ? 2u : 0u)
                         | (a4.z > 0.f ? 4u : 0u) | (a4.w > 0.f ? 8u : 0u);
            bool nz = nzm != 0u;
            unsigned m = __ballot_sync(FULLM, nz);
            if (m) {
                int e0 = __ffs(nzm) - 1;
                float a0 = (e0 <= 0) ? a4.x : (e0 == 1) ? a4.y
                         : (e0 == 2) ? a4.z : a4.w;
                int pos = cnt + __popc(m & ltm);
                bool ovf = nz && pos >= QEFF;
                if (nz && !ovf) {
                    int j = (base4 + k * 32 + lane) * 4 + e0;
                    q[w][pos] = make_float2(a0, __int_as_float(j * 32));
                }
                exm |= (nz ? (nzm & (nzm - 1u)) : 0u) << (kk * 4);
                if (ovf) ovm |= 1u << kk;
                cnt = min(cnt + __popc(m), QEFF);
            }
        }
        unsigned mo = __ballot_sync(FULLM, (exm | ovm) != 0u);
        while (mo) {   // rare (P ~ 1% per warp-half)
            int src = __ffs(mo) - 1; mo &= mo - 1;
            unsigned sex = __shfl_sync(FULLM, exm, src);
            unsigned sov = __shfl_sync(FULLM, ovm, src);
            #pragma unroll
            for (int kk = 0; kk < 4; kk++) {
                unsigned tk = (sex >> (kk * 4)) & 0xFu;
                if (sov & (1u << kk)) tk = 0xFu;   // overflow: redo float4
                if (tk) {
                    const int k = kbase + kk;
                    float4 a4 = stage[w][k * 32 + src];   // reload, no shfl
                    int jb = (base4 + k * 32 + src) * 4;
                    while (tk) {
                        int e = __ffs(tk) - 1; tk &= tk - 1;
                        float a = (e == 0) ? a4.x : (e == 1) ? a4.y
                                : (e == 2) ? a4.z : a4.w;
                        if (a > 0.f) {
                            const ulonglong2* yr = WU + (jb + e) * 32 + hl;
                            float p = dot8(yr[0], yr[16]);
                            if (lane == 0) {
                                float rr = a - (p + ci);
                                acc = fmaf(0.5f * rr, rr, acc);
                            }
                        }
                    }
                }
            }
        }
    };

    // first half ready -> compact while second half still streams in
    asm volatile("cp.async.wait_group 1;");
    __syncwarp();
    compact_half(0);
    asm volatile("cp.async.wait_group 0;");
    __syncwarp();
    compact_half(4);

    // single drain: 4 entries per iteration, all 8 W-loads before any reduce
    {
        int cntp = (cnt + 3) & ~3;
        if (lane < cntp - cnt) q[w][cnt + lane] = make_float2(0.f, 0.f);
        __syncwarp();
        for (int base = 0; base < cntp; base += 4) {
            float2 eA = q[w][base + grp];       // 1x LDS.64 each
            float2 eB = q[w][base + 2 + grp];
            int jA = __float_as_int(eA.y);
            int jB = __float_as_int(eB.y);
            const ulonglong2* ya = WU + jA + hl;
            const ulonglong2* yb = WU + jB + hl;
            ulonglong2 za0 = ya[0], za1 = ya[16];
            ulonglong2 zb0 = yb[0], zb1 = yb[16];
            float pA = dot8(za0, za1);
            if (eA.x > 0.f && hl == 0) {
                float rr = eA.x - (pA + ci);
                acc = fmaf(0.5f * rr, rr, acc);
            }
            float pB = dot8(zb0, zb1);
            if (eB.x > 0.f && hl == 0) {
                float rr = eB.x - (pB + ci);
                acc = fmaf(0.5f * rr, rr, acc);
            }
        }
    }

    // block reduce (sums per-lane rl partials + per-group dot partials)
    #pragma unroll
    for (int off = 16; off > 0; off >>= 1)
        acc += __shfl_xor_sync(FULLM, acc, off);
    if (lane == 0) sp[w] = acc;
    __syncthreads();

    if (threadIdx.x == 0) {
        float part = 0.f;
        #pragma unroll
        for (int i = 0; i < 8; i++) part += sp[i];
        atomicAdd(&g_sum, part);
        __threadfence();
        unsigned c = atomicAdd(&g_count, 1u);
        if (c == gridDim.x - 1) {
            float total = atomicExch(&g_sum, 0.f);
            atomicExch(&g_count, 0u);
            out[0] = total;
        }
    }
}

extern "C" void kernel_launch(void* const* d_in, const int* in_sizes, int n_in,
                              void* d_out, int out_size) {
    const float* A = (const float*)d_in[0];
    const float* W = (const float*)d_in[1];
    const float* b = (const float*)d_in[2];
    float* out = (float*)d_out;

    main_kernel<<<GN, 256>>>(A, W, b, out);
}